// round 13
// baseline (speedup 1.0000x reference)
#include <cuda_runtime.h>
#include <math.h>

#define Bv 32
#define Sv 2048
#define Ev 1024
#define Dv 1024

// Scratch (no device allocations)
__device__ float g_pp [Bv * 128];          // hp partials per (batch, itile)
__device__ float g_qp4[4][Bv * Ev];        // q partials: 4 d-chunks
__device__ float g_c  [Bv];
__device__ float g_p  [Bv];
__device__ float g_att[Bv * Sv];
__device__ int   g_qcnt;                   // q/c producers done   (self-reset)
__device__ int   g_pass;                   // att blocks past spin (self-reset)
__device__ int   g_hcnt;                   // hp blocks done       (self-reset)
__device__ int   g_pdone;                  // p finalized          (self-reset)
__device__ int   g_acnt[Bv];               // att blocks done per batch
__device__ int   g_fb  [Bv];               // fin blocks past per batch
__device__ int   g_ftot;                   // fin blocks past total

__device__ __forceinline__ float warp_sum(float v) {
#pragma unroll
    for (int o = 16; o > 0; o >>= 1) v += __shfl_xor_sync(0xffffffffu, v, o);
    return v;
}
__device__ __forceinline__ float warp_max(float v) {
#pragma unroll
    for (int o = 16; o > 0; o >>= 1) v = fmaxf(v, __shfl_xor_sync(0xffffffffu, v, o));
    return v;
}

// ---------------------------------------------------------------------------
// k_main: 2080 blocks x 256 threads, ONE node, four block classes:
//   [0,256)     q partials             -> g_qcnt
//   [256,288)   c[b]                   -> g_qcnt
//   [288,800)   hp partials; last block finalizes p[b], sets g_pdone
//   [800,1824)  att: spin g_qcnt==288; per-batch done -> g_acnt[b]
//   [1824,2080) fin: spin g_acnt[b]==32 && g_pdone; softmax+alpha+awe
// ---------------------------------------------------------------------------
__global__ void __launch_bounds__(256) k_main(const float* __restrict__ enc,
                      const float* __restrict__ vp_b,
                      const float* __restrict__ h,
                      const float* __restrict__ Wa_w,
                      const float* __restrict__ Wa_b,
                      const float* __restrict__ Wp_w,
                      const float* __restrict__ Wp_b,
                      const float* __restrict__ vp_w,
                      float* __restrict__ awe,
                      float* __restrict__ alpha) {
    __shared__ float4 sbuf[2048];          // 32 KB, aliased by all classes
    int bid = blockIdx.x, t = threadIdx.x;

    if (bid < 256) {
        // ---- q partial path ----
        float*  hs  = (float*)sbuf;        // [4][256] = 4 KB
        float4* red = sbuf + 256;          // [8 dg][4 k][32 col] = 16 KB
        int et = bid & 7;
        int dc = (bid >> 3) & 3;
        int bg = bid >> 5;
        int b0 = bg * 4, d0 = dc * 256, e0 = et * 128;
        for (int idx = t; idx < 4 * 256; idx += 256) {
            int k = idx >> 8, d = idx & 255;
            hs[k * 256 + d] = h[(size_t)(b0 + k) * Dv + d0 + d];
        }
        __syncthreads();
        int col = t & 31, dg = t >> 5;
        float4 acc[4];
#pragma unroll
        for (int k = 0; k < 4; k++) acc[k] = make_float4(0.f, 0.f, 0.f, 0.f);
#pragma unroll 4
        for (int i = 0; i < 32; i++) {
            int d = dg * 32 + i;
            float4 wv = ((const float4*)(Wa_w + (size_t)(d0 + d) * Ev + e0))[col];
#pragma unroll
            for (int k = 0; k < 4; k++) {
                float x = hs[k * 256 + d];
                acc[k].x += wv.x * x; acc[k].y += wv.y * x;
                acc[k].z += wv.z * x; acc[k].w += wv.w * x;
            }
        }
#pragma unroll
        for (int k = 0; k < 4; k++) red[(dg * 4 + k) * 32 + col] = acc[k];
        __syncthreads();
#pragma unroll
        for (int o = 4; o > 0; o >>= 1) {
            if (dg < o) {
#pragma unroll
                for (int k = 0; k < 4; k++) {
                    float4 u = red[(dg * 4 + k) * 32 + col];
                    float4 v = red[((dg + o) * 4 + k) * 32 + col];
                    u.x += v.x; u.y += v.y; u.z += v.z; u.w += v.w;
                    red[(dg * 4 + k) * 32 + col] = u;
                }
            }
            __syncthreads();
        }
        if (dg == 0) {
#pragma unroll
            for (int k = 0; k < 4; k++)
                ((float4*)(g_qp4[dc] + (size_t)(b0 + k) * Ev + e0))[col] =
                    red[k * 32 + col];
        }
        __threadfence();
        __syncthreads();
        if (t == 0) atomicAdd(&g_qcnt, 1);
        return;
    }
    if (bid < 288) {
        // ---- c path ----
        int b = bid - 256;
        float v = 0.f;
        for (int d = t; d < Dv; d += 256) v += h[b * Dv + d] * Wa_b[d];
        v = warp_sum(v);
        __shared__ float redc[8];
        if ((t & 31) == 0) redc[t >> 5] = v;
        __syncthreads();
        if (t == 0) {
            float s = 0.f;
#pragma unroll
            for (int i = 0; i < 8; i++) s += redc[i];
            g_c[b] = s;
            __threadfence();
            atomicAdd(&g_qcnt, 1);
        }
        return;
    }
    if (bid < 800) {
        // ---- hp path: 8 i per block, 8 batches ----
        float4 (*hs4)[256] = (float4(*)[256])sbuf;   // 32 KB
        __shared__ float wtmp[8][8];
        int id = bid - 288;
        int b0 = (id >> 7) * 8;
        int itile = id & 127;
        for (int idx = t; idx < 8 * 256; idx += 256) {
            int k = idx >> 8, j = idx & 255;
            hs4[k][j] = ((const float4*)(h + (size_t)(b0 + k) * Dv))[j];
        }
        __syncthreads();
        int w = t >> 5, lane = t & 31;
        int i = itile * 8 + w;
        const float4* wr = (const float4*)(Wp_w + (size_t)i * Dv);
        float acc[8];
#pragma unroll
        for (int k = 0; k < 8; k++) acc[k] = 0.f;
#pragma unroll
        for (int j = lane; j < 256; j += 32) {
            float4 wv = wr[j];
#pragma unroll
            for (int k = 0; k < 8; k++) {
                float4 x = hs4[k][j];
                acc[k] += wv.x * x.x + wv.y * x.y + wv.z * x.z + wv.w * x.w;
            }
        }
#pragma unroll
        for (int k = 0; k < 8; k++) acc[k] = warp_sum(acc[k]);
        if (lane == 0) {
            float bia = Wp_b[i];
            float vp  = vp_w[i];
#pragma unroll
            for (int k = 0; k < 8; k++) wtmp[w][k] = tanhf(acc[k] + bia) * vp;
        }
        __syncthreads();
        if (t < 8) {
            float s = 0.f;
#pragma unroll
            for (int w2 = 0; w2 < 8; w2++) s += wtmp[w2][t];
            g_pp[(b0 + t) * 128 + itile] = s;
        }
        __threadfence();
        __syncthreads();
        __shared__ int hlast;
        if (t == 0) hlast = (atomicAdd(&g_hcnt, 1) == 511);
        __syncthreads();
        if (hlast) {
            __threadfence();
            int b = t >> 3, part = t & 7;
            float s = 0.f;
#pragma unroll
            for (int j = part; j < 128; j += 8) s += g_pp[b * 128 + j];
#pragma unroll
            for (int o = 4; o > 0; o >>= 1) s += __shfl_xor_sync(0xffffffffu, s, o);
            if (part == 0) {
                float x = s + vp_b[0];
                g_p[b] = (float)Sv / (1.f + expf(-x));
            }
            __syncthreads();
            if (t == 0) {
                g_hcnt = 0;
                __threadfence();
                g_pdone = 1;
            }
        }
        return;
    }
    if (bid < 1824) {
        // ---- att path ----
        int id = bid - 800;
        int tile = id & 31, b = id >> 5;

        if (t == 0) {
            while (*(volatile int*)&g_qcnt < 288) {}
            if (atomicAdd(&g_pass, 1) == 1023) { g_qcnt = 0; g_pass = 0; }
        }
        __syncthreads();
        __threadfence();

        float4* qs = sbuf;                 // 4 KB
        {
            float4 s0 = ((const float4*)(g_qp4[0] + b * Ev))[t];
            float4 s1 = ((const float4*)(g_qp4[1] + b * Ev))[t];
            float4 s2 = ((const float4*)(g_qp4[2] + b * Ev))[t];
            float4 s3 = ((const float4*)(g_qp4[3] + b * Ev))[t];
            float4 r;
            r.x = (s0.x + s1.x) + (s2.x + s3.x);
            r.y = (s0.y + s1.y) + (s2.y + s3.y);
            r.z = (s0.z + s1.z) + (s2.z + s3.z);
            r.w = (s0.w + s1.w) + (s2.w + s3.w);
            qs[t] = r;
        }
        __syncthreads();

        int w = t >> 5, lane = t & 31;
        float c = g_c[b];
#pragma unroll
        for (int r = 0; r < 8; r += 2) {
            int s = tile * 64 + w * 8 + r;
            const float4* er0 = (const float4*)(enc + ((size_t)b * Sv + s)     * Ev);
            const float4* er1 = (const float4*)(enc + ((size_t)b * Sv + s + 1) * Ev);
            float acc0 = 0.f, acc1 = 0.f;
#pragma unroll
            for (int j = lane; j < Ev / 4; j += 32) {
                float4 x  = qs[j];
                float4 a0 = __ldcs(er0 + j);
                float4 a1 = __ldcs(er1 + j);
                acc0 += a0.x * x.x + a0.y * x.y + a0.z * x.z + a0.w * x.w;
                acc1 += a1.x * x.x + a1.y * x.y + a1.z * x.z + a1.w * x.w;
            }
            acc0 = warp_sum(acc0);
            acc1 = warp_sum(acc1);
            if (lane == 0) {
                g_att[b * Sv + s]     = acc0 + c;
                g_att[b * Sv + s + 1] = acc1 + c;
            }
        }
        __threadfence();
        __syncthreads();
        if (t == 0) atomicAdd(&g_acnt[b], 1);
        return;
    }

    // ---- fin path: 8 e-tiles x 32 batches ----
    {
        int id = bid - 1824;
        int tile = id & 7, b = id >> 3;
        int lane = t & 31, wrp = t >> 5;
        __shared__ float red[8];
        __shared__ float fin;
        __shared__ float aw[64];
        float4 (*pacc)[32] = (float4(*)[32])sbuf;   // [8][32] float4 = 4 KB

        if (t == 0) {
            while (*(volatile int*)&g_acnt[b] < 32) {}
            while (*(volatile int*)&g_pdone == 0) {}
            if (atomicAdd(&g_fb[b], 1) == 7)  { g_acnt[b] = 0; g_fb[b] = 0; }
            if (atomicAdd(&g_ftot, 1) == 255) { g_pdone = 0;  g_ftot = 0; }
        }
        __syncthreads();
        __threadfence();

        float p = g_p[b];
        int lo = (int)floorf(p) - 31;
        if (lo < 0) lo = 0;
        if (lo > Sv - 64) lo = Sv - 64;

        // softmax stats: 8 att values per thread
        float av[8];
        float m = -1e30f;
#pragma unroll
        for (int i = 0; i < 8; i++) {
            av[i] = g_att[b * Sv + i * 256 + t];
            m = fmaxf(m, av[i]);
        }
        m = warp_max(m);
        if (lane == 0) red[wrp] = m;
        __syncthreads();
        if (wrp == 0) {
            float v = (lane < 8) ? red[lane] : -1e30f;
            v = warp_max(v);
            if (lane == 0) fin = v;
        }
        __syncthreads();
        float mb = fin;
        float l = 0.f;
#pragma unroll
        for (int i = 0; i < 8; i++) { av[i] = expf(av[i] - mb); l += av[i]; }
        l = warp_sum(l);
        __syncthreads();
        if (lane == 0) red[wrp] = l;
        __syncthreads();
        if (wrp == 0) {
            float v = (lane < 8) ? red[lane] : 0.f;
            v = warp_sum(v);
            if (lane == 0) fin = v;
        }
        __syncthreads();
        float inv = 1.f / fin;
#pragma unroll
        for (int i = 0; i < 8; i++) {
            int s = i * 256 + t;
            float d = (float)s - p;
            float al = av[i] * inv * expf(-d * d * 0.125f);
            if (tile == 0) alpha[b * Sv + s] = al;
            int wo = s - lo;
            if ((unsigned)wo < 64u) aw[wo] = al;
        }
        __syncthreads();

        // windowed awe slice (128 cols): 8 rows per thread, branchless.
        // alpha outside |s-p|<=29 is exactly 0 (fp32 underflow, identical
        // in the reference).
        int col = t & 31, rg = t >> 5;
        const float4* base = (const float4*)(enc + ((size_t)b * Sv + lo) * Ev)
                             + tile * 32;
        float4 acc = make_float4(0.f, 0.f, 0.f, 0.f);
#pragma unroll
        for (int i = 0; i < 8; i++) {
            int sl = rg * 8 + i;
            float a = aw[sl];
            float4 v = base[(size_t)sl * (Ev / 4) + col];
            acc.x += v.x * a; acc.y += v.y * a; acc.z += v.z * a; acc.w += v.w * a;
        }
        pacc[rg][col] = acc;
        __syncthreads();
#pragma unroll
        for (int o = 4; o > 0; o >>= 1) {
            if (rg < o) {
                float4 u = pacc[rg][col], v = pacc[rg + o][col];
                u.x += v.x; u.y += v.y; u.z += v.z; u.w += v.w;
                pacc[rg][col] = u;
            }
            __syncthreads();
        }
        if (t < 32)
            ((float4*)(awe + b * Ev + tile * 128))[t] = pacc[0][t];
    }
}

extern "C" void kernel_launch(void* const* d_in, const int* in_sizes, int n_in,
                              void* d_out, int out_size) {
    const float* enc  = (const float*)d_in[0];   // [B,S,E]
    const float* h    = (const float*)d_in[1];   // [B,D]
    const float* Wa_w = (const float*)d_in[3];   // [D,E]
    const float* Wa_b = (const float*)d_in[4];   // [D]
    const float* Wp_w = (const float*)d_in[5];   // [D,D]
    const float* Wp_b = (const float*)d_in[6];   // [D]
    const float* vp_w = (const float*)d_in[7];   // [1,D]
    const float* vp_b = (const float*)d_in[8];   // [1]

    float* awe   = (float*)d_out;                 // [B,E]
    float* alpha = (float*)d_out + Bv * Ev;       // [B,S]

    k_main<<<2080, 256>>>(enc, vp_b, h, Wa_w, Wa_b, Wp_w, Wp_b, vp_w,
                          awe, alpha);
}